// round 2
// baseline (speedup 1.0000x reference)
#include <cuda_runtime.h>
#include <cuda_bf16.h>
#include <cstdint>

#define NS 64
#define ND 32
#define NB 32
#define NT 1024
#define NF 64
#define NC 128
#define NEGV (-1e30f)
#define L2E 1.4426950408889634f
#define LN2 0.6931471805599453f

// ---------------- scratch (static device globals; no allocation) ----------------
__device__ float g_h[10240];            // hidden activations: [0:4096) A, [4096:6144) D, [6144:10240) E
__device__ float g_dA[4096];
__device__ float g_dD[2048];
__device__ float g_dE[4096];
__device__ float g_A[NS * NS];          // linear-domain softmax probs A[s_from][s_to]
__device__ float g_logDurT[ND * NS];    // [d][s], base-2 scaled
__device__ float g_invT[NF * NS];       // [f][s]
__device__ float g_W2T[NF * NS];        // [f][s] = 2*mu_c*inv
__device__ float g_cst[NS];
__device__ float g_logB[(size_t)NB * NT * NS];  // [b*T+t][s], base-2 scaled

// ---------------- fast math helpers ----------------
__device__ __forceinline__ float ex2f(float x) {
    float y; asm("ex2.approx.ftz.f32 %0, %1;" : "=f"(y) : "f"(x)); return y;
}
__device__ __forceinline__ float lg2f(float x) {
    float y; asm("lg2.approx.f32 %0, %1;" : "=f"(y) : "f"(x)); return y;
}

__device__ __forceinline__ float* pick(int which) {
    switch (which) {
        case 0: return g_h;
        case 1: return g_h + 4096;
        case 2: return g_h + 6144;
        case 3: return g_dA;
        case 4: return g_dD;
        case 5: return g_dE;
    }
    return nullptr;
}

// ---------------- generic matvec: out[row] = (tanh?)(W[row,:] . in + b[row]) ----------------
__global__ void linear_kernel(const float* __restrict__ W, const float* __restrict__ bias,
                              const float* __restrict__ in_ext, int in_sel, int out_sel,
                              int n_out, int n_in, int do_tanh)
{
    __shared__ float sin_[4096];
    const float* in = in_ext ? in_ext : pick(in_sel);
    float* out = pick(out_sel);
    for (int i = threadIdx.x; i < n_in; i += blockDim.x) sin_[i] = in[i];
    __syncthreads();

    int row  = (int)((blockIdx.x * blockDim.x + threadIdx.x) >> 5);
    int lane = threadIdx.x & 31;
    if (row >= n_out) return;

    const float4* Wr = (const float4*)(W + (size_t)row * n_in);
    const float4* vr = (const float4*)sin_;
    float acc = 0.f;
    int n4 = n_in >> 2;
    for (int k = lane; k < n4; k += 32) {
        float4 w = Wr[k], v = vr[k];
        acc = fmaf(w.x, v.x, acc); acc = fmaf(w.y, v.y, acc);
        acc = fmaf(w.z, v.z, acc); acc = fmaf(w.w, v.w, acc);
    }
#pragma unroll
    for (int o = 16; o; o >>= 1) acc += __shfl_xor_sync(0xffffffffu, acc, o);
    if (lane == 0) {
        float r = acc + bias[row];
        out[row] = do_tanh ? tanhf(r) : r;
    }
}

// ---------------- postprocess: softmaxes + emission params (1 block per state s, 32 thr) ----------------
__global__ void post_kernel(const float* __restrict__ A_logits, const float* __restrict__ D_logits,
                            const float* __restrict__ mu, const float* __restrict__ log_var)
{
    int s = blockIdx.x, lane = threadIdx.x;

    // --- A row softmax (linear domain output) ---
    int i0 = s * NS + lane;
    float z0 = A_logits[i0]      + 0.1f * tanhf(g_dA[i0]);
    float z1 = A_logits[i0 + 32] + 0.1f * tanhf(g_dA[i0 + 32]);
    float m = fmaxf(z0, z1);
#pragma unroll
    for (int o = 16; o; o >>= 1) m = fmaxf(m, __shfl_xor_sync(0xffffffffu, m, o));
    float e0 = expf(z0 - m), e1 = expf(z1 - m);
    float ss = e0 + e1;
#pragma unroll
    for (int o = 16; o; o >>= 1) ss += __shfl_xor_sync(0xffffffffu, ss, o);
    float inv_ss = 1.f / ss;
    g_A[i0] = e0 * inv_ss;
    g_A[i0 + 32] = e1 * inv_ss;

    // --- Dur row log-softmax (transposed, base-2 scaled) ---
    int id = s * ND + lane;
    float zd = D_logits[id] + 0.1f * tanhf(g_dD[id]);
    float md = zd;
#pragma unroll
    for (int o = 16; o; o >>= 1) md = fmaxf(md, __shfl_xor_sync(0xffffffffu, md, o));
    float ed = expf(zd - md);
    float sd = ed;
#pragma unroll
    for (int o = 16; o; o >>= 1) sd += __shfl_xor_sync(0xffffffffu, sd, o);
    g_logDurT[lane * NS + s] = (zd - md - logf(sd)) * L2E;

    // --- emission params ---
    float cp = 0.f;
#pragma unroll
    for (int half = 0; half < 2; half++) {
        int f = lane + half * 32;
        int ie = s * NF + f;
        float mc = mu[ie] + 0.1f * tanhf(g_dE[ie]);
        float lv = log_var[ie];
        float sp = (lv > 20.f) ? lv : log1pf(expf(lv));
        float v = sp + 0.001f;
        float iv = 1.f / v;
        g_invT[f * NS + s] = iv;
        g_W2T[f * NS + s] = 2.f * mc * iv;
        cp += mc * mc * iv + logf(v);
    }
#pragma unroll
    for (int o = 16; o; o >>= 1) cp += __shfl_xor_sync(0xffffffffu, cp, o);
    if (lane == 0) g_cst[s] = cp + (float)NF * 1.8378770664093453f;  // + F*log(2*pi)
}

// ---------------- emission log-likelihoods: logB[bt][s] (base-2 scaled) ----------------
// 32 bt-rows per block: smem = 8KB(x) + 16KB(inv) + 16KB(w2) + 256B = 40.25KB < 48KB static limit
__global__ void logb_kernel(const float* __restrict__ x)
{
    __shared__ float xs[32 * 64];
    __shared__ float ivs[64 * 64];
    __shared__ float w2s[64 * 64];
    __shared__ float csts[64];
    int tid = threadIdx.x;
    size_t bt0 = (size_t)blockIdx.x * 32;

    for (int i = tid; i < 4096; i += 256) {
        ivs[i] = g_invT[i];
        w2s[i] = g_W2T[i];
    }
    for (int i = tid; i < 2048; i += 256) xs[i] = x[bt0 * NF + i];
    if (tid < 64) csts[tid] = g_cst[tid];
    __syncthreads();

    int s = tid & 63, rg = tid >> 6;
    float acc[8];
#pragma unroll
    for (int k = 0; k < 8; k++) acc[k] = 0.f;

#pragma unroll 4
    for (int f = 0; f < NF; f++) {
        float iv = ivs[f * 64 + s];
        float w2 = w2s[f * 64 + s];
#pragma unroll
        for (int k = 0; k < 8; k++) {
            float xv = xs[(rg * 8 + k) * 64 + f];
            acc[k] = fmaf(xv, fmaf(iv, xv, -w2), acc[k]);
        }
    }
    float c = csts[s];
    const float sc = -0.5f * L2E;
#pragma unroll
    for (int k = 0; k < 8; k++)
        g_logB[(bt0 + rg * 8 + k) * NS + s] = (acc[k] + c) * sc;
}

// ---------------- the sequential HSMM scan: one CTA per batch ----------------
// Thread layout: tid = s*4 + p  (s = state 0..63, p = partition 0..3).
// Ring holds G_t[s] = trans_t[s] - Ccum[t+1][s] (base-2). Slot 31 seeded with
// log2(1/S) implements the is_init (d == t+1) case; untouched slots hold NEG.
__global__ void __launch_bounds__(256, 1) scan_kernel(float* __restrict__ out)
{
    __shared__ float G[ND][65];       // padded: conflict-free for stride-8 slot access
    __shared__ float alpha_sh[NS];

    int b = blockIdx.x;
    int tid = threadIdx.x;
    int s = tid >> 2, p = tid & 3;

    // per-thread constants in registers
    float ldur[8];
#pragma unroll
    for (int j = 0; j < 8; j++) ldur[j] = g_logDurT[(p * 8 + j) * NS + s];
    float Areg[16];
    int spbase = p * 16;
#pragma unroll
    for (int i = 0; i < 16; i++) {
        int sp = spbase + ((i + 4 * p) & 15);      // rotated to spread smem banks
        Areg[i] = g_A[sp * NS + s];
    }

    for (int i = tid; i < ND * 65; i += 256) (&G[0][0])[i] = NEGV;
    __syncthreads();
    if (tid < NS) G[31][tid] = -6.0f;              // log2(1/64)
    __syncthreads();

    float Ccum = 0.f;
    const float* lbp = g_logB + (size_t)b * NT * NS + s;
    float lb = lbp[0];                              // software prefetch

    float m2 = 0.f, av[16];
    for (int t = 0; t < NT; t++) {
        Ccum += lb;
        if (t + 1 < NT) lb = lbp[(size_t)(t + 1) * NS];

        // ---- alpha[s] = Ccum + lse_d( G[t-d][s] + logDur[d][s] ) ----
        float term[8], mx = -3.4e38f;
#pragma unroll
        for (int j = 0; j < 8; j++) {
            int slot = (t - 1 - 8 * p - j) & 31;    // d = 8p + j + 1
            term[j] = G[slot][s] + ldur[j];
            mx = fmaxf(mx, term[j]);
        }
        mx = fmaxf(mx, __shfl_xor_sync(0xffffffffu, mx, 1));
        mx = fmaxf(mx, __shfl_xor_sync(0xffffffffu, mx, 2));
        float sum = 0.f;
#pragma unroll
        for (int j = 0; j < 8; j++) sum += ex2f(term[j] - mx);
        sum += __shfl_xor_sync(0xffffffffu, sum, 1);
        sum += __shfl_xor_sync(0xffffffffu, sum, 2);
        if (p == 0) alpha_sh[s] = Ccum + mx + lg2f(sum);
        __syncthreads();

        // ---- trans[s] = lse_{s'}(alpha[s'] + logA[s',s]) via linear-domain matvec ----
        m2 = -3.4e38f;
#pragma unroll
        for (int i = 0; i < 16; i++) {
            int sp = spbase + ((i + 4 * p) & 15);
            av[i] = alpha_sh[sp];
            m2 = fmaxf(m2, av[i]);
        }
        m2 = fmaxf(m2, __shfl_xor_sync(0xffffffffu, m2, 1));
        m2 = fmaxf(m2, __shfl_xor_sync(0xffffffffu, m2, 2));
        float q = 0.f;
#pragma unroll
        for (int i = 0; i < 16; i++) q = fmaf(Areg[i], ex2f(av[i] - m2), q);
        q += __shfl_xor_sync(0xffffffffu, q, 1);
        q += __shfl_xor_sync(0xffffffffu, q, 2);
        if (p == 0) G[t & 31][s] = m2 + lg2f(q) - Ccum;
        __syncthreads();
    }

    // ---- out[b] = lse_s alpha_{T-1}[s]  (convert base-2 -> natural log) ----
    float fs = 0.f;
#pragma unroll
    for (int i = 0; i < 16; i++) fs += ex2f(av[i] - m2);
    fs += __shfl_xor_sync(0xffffffffu, fs, 1);
    fs += __shfl_xor_sync(0xffffffffu, fs, 2);
    if (tid == 0) out[b] = (m2 + lg2f(fs)) * LN2;
}

// ---------------- host launcher ----------------
extern "C" void kernel_launch(void* const* d_in, const int* in_sizes, int n_in,
                              void* d_out, int out_size)
{
    const float* x        = (const float*)d_in[0];
    const float* context  = (const float*)d_in[1];
    const float* A_logits = (const float*)d_in[2];
    const float* D_logits = (const float*)d_in[3];
    const float* mu       = (const float*)d_in[4];
    const float* log_var  = (const float*)d_in[5];
    const float* tA_w1 = (const float*)d_in[6],  *tA_b1 = (const float*)d_in[7];
    const float* tA_w2 = (const float*)d_in[8],  *tA_b2 = (const float*)d_in[9];
    const float* tD_w1 = (const float*)d_in[10], *tD_b1 = (const float*)d_in[11];
    const float* tD_w2 = (const float*)d_in[12], *tD_b2 = (const float*)d_in[13];
    const float* tE_w1 = (const float*)d_in[14], *tE_b1 = (const float*)d_in[15];
    const float* tE_w2 = (const float*)d_in[16], *tE_b2 = (const float*)d_in[17];

    // hidden layers: h = tanh(W1 @ ctx + b1)
    linear_kernel<<<(4096 + 7) / 8, 256>>>(tA_w1, tA_b1, context, -1, 0, 4096, NC, 1);
    linear_kernel<<<(2048 + 7) / 8, 256>>>(tD_w1, tD_b1, context, -1, 1, 2048, NC, 1);
    linear_kernel<<<(4096 + 7) / 8, 256>>>(tE_w1, tE_b1, context, -1, 2, 4096, NC, 1);
    // output layers: d = W2 @ h + b2
    linear_kernel<<<(4096 + 7) / 8, 256>>>(tA_w2, tA_b2, nullptr, 0, 3, 4096, 4096, 0);
    linear_kernel<<<(2048 + 7) / 8, 256>>>(tD_w2, tD_b2, nullptr, 1, 4, 2048, 2048, 0);
    linear_kernel<<<(4096 + 7) / 8, 256>>>(tE_w2, tE_b2, nullptr, 2, 5, 4096, 4096, 0);
    // softmaxes + emission params
    post_kernel<<<NS, 32>>>(A_logits, D_logits, mu, log_var);
    // emission log-likelihoods
    logb_kernel<<<(NB * NT) / 32, 256>>>(x);
    // the sequential forward scan (one CTA per batch, persistent)
    scan_kernel<<<NB, 256>>>((float*)d_out);
}

// round 5
// speedup vs baseline: 2.3727x; 2.3727x over previous
#include <cuda_runtime.h>
#include <cuda_bf16.h>
#include <cstdint>

#define NS 64
#define ND 32
#define NB 32
#define NT 1024
#define NF 64
#define NC 128
#define L2E 1.4426950408889634f
#define LN2D 0.6931471805599453

// ---------------- scratch (static device globals; no allocation) ----------------
__device__ float g_h[10240];            // hidden activations: [0:4096) A, [4096:6144) D, [6144:10240) E
__device__ float g_dA[4096];
__device__ float g_dD[2048];
__device__ float g_dE[4096];
__device__ float g_AT[NS * NS];         // A transposed: g_AT[s_to*64 + s_from] (linear probs)
__device__ float g_DurT[ND * NS];       // linear duration probs [d0][s] (d0 = d-1)
__device__ float g_invT[NF * NS];
__device__ float g_W2T[NF * NS];
__device__ float g_cst[NS];
__device__ float g_z[(size_t)NB * NT * NS + 4 * NS];    // 2^(logB - c), padded 4 steps
__device__ float g_c[NB * NT];                          // per-(b,t) max_s base-2 logB
__device__ double g_csum[NB];                           // sum_t c

// ---------------- fast math helpers ----------------
__device__ __forceinline__ float ex2f(float x) {
    float y; asm("ex2.approx.ftz.f32 %0, %1;" : "=f"(y) : "f"(x)); return y;
}
__device__ __forceinline__ float lg2f(float x) {
    float y; asm("lg2.approx.f32 %0, %1;" : "=f"(y) : "f"(x)); return y;
}

// ---------------- fused first-layer matvecs: h = tanh(W1 @ ctx + b1), all 3 MLPs ---------------
__global__ void lin1_kernel(const float* __restrict__ ctx,
                            const float* __restrict__ wA, const float* __restrict__ bA,
                            const float* __restrict__ wD, const float* __restrict__ bD,
                            const float* __restrict__ wE, const float* __restrict__ bE)
{
    __shared__ float sin_[NC];
    if (threadIdx.x < NC) sin_[threadIdx.x] = ctx[threadIdx.x];
    __syncthreads();

    int row  = (int)((blockIdx.x * blockDim.x + threadIdx.x) >> 5);
    int lane = threadIdx.x & 31;

    const float* W; const float* bias; float* out; int r;
    if (row < 4096)      { W = wA; bias = bA; out = g_h;        r = row; }
    else if (row < 6144) { W = wD; bias = bD; out = g_h + 4096; r = row - 4096; }
    else                 { W = wE; bias = bE; out = g_h + 6144; r = row - 6144; }

    float4 w = ((const float4*)(W + (size_t)r * NC))[lane];
    float4 v = ((const float4*)sin_)[lane];
    float acc = w.x * v.x;
    acc = fmaf(w.y, v.y, acc); acc = fmaf(w.z, v.z, acc); acc = fmaf(w.w, v.w, acc);
#pragma unroll
    for (int o = 16; o; o >>= 1) acc += __shfl_xor_sync(0xffffffffu, acc, o);
    if (lane == 0) out[r] = tanhf(acc + bias[r]);
}

// ---------------- fused second-layer matvecs: d = W2 @ h + b2, all 3 MLPs ----------------
// Warp per row; 4-deep float4 load batching for DRAM MLP. Segment sizes divisible
// by 8 rows/block so no block straddles a segment boundary.
__global__ void lin2_kernel(const float* __restrict__ wA, const float* __restrict__ bA,
                            const float* __restrict__ wD, const float* __restrict__ bD,
                            const float* __restrict__ wE, const float* __restrict__ bE)
{
    __shared__ float sin_[4096];
    int row0 = blockIdx.x * 8;

    const float* in; const float* W; const float* bias; float* out; int n_in, base;
    if (row0 < 4096)      { in = g_h;        n_in = 4096; W = wA; bias = bA; out = g_dA; base = 0; }
    else if (row0 < 6144) { in = g_h + 4096; n_in = 2048; W = wD; bias = bD; out = g_dD; base = 4096; }
    else                  { in = g_h + 6144; n_in = 4096; W = wE; bias = bE; out = g_dE; base = 6144; }

    for (int i = threadIdx.x; i < n_in; i += blockDim.x) sin_[i] = in[i];
    __syncthreads();

    int r    = row0 - base + (int)(threadIdx.x >> 5);
    int lane = threadIdx.x & 31;
    const float4* Wr = (const float4*)(W + (size_t)r * n_in);
    const float4* vr = (const float4*)sin_;
    int n4 = n_in >> 2;                    // 1024 or 512; both multiples of 128

    float a0 = 0.f, a1 = 0.f, a2 = 0.f, a3 = 0.f;
    for (int k = lane; k < n4; k += 128) {
        float4 w0 = Wr[k], w1 = Wr[k + 32], w2 = Wr[k + 64], w3 = Wr[k + 96];
        float4 v0 = vr[k], v1 = vr[k + 32], v2 = vr[k + 64], v3 = vr[k + 96];
        a0 = fmaf(w0.x, v0.x, a0); a0 = fmaf(w0.y, v0.y, a0);
        a0 = fmaf(w0.z, v0.z, a0); a0 = fmaf(w0.w, v0.w, a0);
        a1 = fmaf(w1.x, v1.x, a1); a1 = fmaf(w1.y, v1.y, a1);
        a1 = fmaf(w1.z, v1.z, a1); a1 = fmaf(w1.w, v1.w, a1);
        a2 = fmaf(w2.x, v2.x, a2); a2 = fmaf(w2.y, v2.y, a2);
        a2 = fmaf(w2.z, v2.z, a2); a2 = fmaf(w2.w, v2.w, a2);
        a3 = fmaf(w3.x, v3.x, a3); a3 = fmaf(w3.y, v3.y, a3);
        a3 = fmaf(w3.z, v3.z, a3); a3 = fmaf(w3.w, v3.w, a3);
    }
    float acc = (a0 + a1) + (a2 + a3);
#pragma unroll
    for (int o = 16; o; o >>= 1) acc += __shfl_xor_sync(0xffffffffu, acc, o);
    if (lane == 0) out[r] = acc + bias[r];
}

// ---------------- postprocess: softmaxes + emission params (1 block per state s, 32 thr) --------
__global__ void post_kernel(const float* __restrict__ A_logits, const float* __restrict__ D_logits,
                            const float* __restrict__ mu, const float* __restrict__ log_var)
{
    int s = blockIdx.x, lane = threadIdx.x;

    // --- A row softmax -> linear probs, stored transposed ---
    int i0 = s * NS + lane;
    float z0 = A_logits[i0]      + 0.1f * tanhf(g_dA[i0]);
    float z1 = A_logits[i0 + 32] + 0.1f * tanhf(g_dA[i0 + 32]);
    float m = fmaxf(z0, z1);
#pragma unroll
    for (int o = 16; o; o >>= 1) m = fmaxf(m, __shfl_xor_sync(0xffffffffu, m, o));
    float e0 = expf(z0 - m), e1 = expf(z1 - m);
    float ss = e0 + e1;
#pragma unroll
    for (int o = 16; o; o >>= 1) ss += __shfl_xor_sync(0xffffffffu, ss, o);
    float inv_ss = 1.f / ss;
    g_AT[lane * NS + s]        = e0 * inv_ss;   // A[s][lane] -> AT[lane][s]
    g_AT[(lane + 32) * NS + s] = e1 * inv_ss;

    // --- Dur row softmax -> linear probs, transposed [d][s] ---
    int id = s * ND + lane;
    float zd = D_logits[id] + 0.1f * tanhf(g_dD[id]);
    float md = zd;
#pragma unroll
    for (int o = 16; o; o >>= 1) md = fmaxf(md, __shfl_xor_sync(0xffffffffu, md, o));
    float ed = expf(zd - md);
    float sd = ed;
#pragma unroll
    for (int o = 16; o; o >>= 1) sd += __shfl_xor_sync(0xffffffffu, sd, o);
    g_DurT[lane * NS + s] = ed / sd;

    // --- emission params ---
    float cp = 0.f;
#pragma unroll
    for (int half = 0; half < 2; half++) {
        int f = lane + half * 32;
        int ie = s * NF + f;
        float mc = mu[ie] + 0.1f * tanhf(g_dE[ie]);
        float lv = log_var[ie];
        float sp = (lv > 20.f) ? lv : log1pf(expf(lv));
        float v = sp + 0.001f;
        float iv = 1.f / v;
        g_invT[f * NS + s] = iv;
        g_W2T[f * NS + s] = 2.f * mc * iv;
        cp += mc * mc * iv + logf(v);
    }
#pragma unroll
    for (int o = 16; o; o >>= 1) cp += __shfl_xor_sync(0xffffffffu, cp, o);
    if (lane == 0) g_cst[s] = cp + (float)NF * 1.8378770664093453f;
}

// ---------------- fused emission + z-prep: z[bt][s] = 2^(logB - c), c = row max ----------------
// logB never touches HBM: computed in registers, row-maxed via smem (xs reused), z written out.
__global__ void logbz_kernel(const float* __restrict__ x)
{
    __shared__ float xs[32 * 64];        // x tile; reused as logB buffer after conv
    __shared__ float ivs[64 * 64];
    __shared__ float w2s[64 * 64];
    __shared__ float csts[64];
    int tid = threadIdx.x;
    size_t bt0 = (size_t)blockIdx.x * 32;

    for (int i = tid; i < 4096; i += 256) {
        ivs[i] = g_invT[i];
        w2s[i] = g_W2T[i];
    }
    for (int i = tid; i < 2048; i += 256) xs[i] = x[bt0 * NF + i];
    if (tid < 64) csts[tid] = g_cst[tid];
    __syncthreads();

    int s = tid & 63, rg = tid >> 6;
    float acc[8];
#pragma unroll
    for (int k = 0; k < 8; k++) acc[k] = 0.f;

#pragma unroll 4
    for (int f = 0; f < NF; f++) {
        float iv = ivs[f * 64 + s];
        float w2 = w2s[f * 64 + s];
#pragma unroll
        for (int k = 0; k < 8; k++) {
            float xv = xs[(rg * 8 + k) * 64 + f];
            acc[k] = fmaf(xv, fmaf(iv, xv, -w2), acc[k]);
        }
    }
    float c = csts[s];
    const float sc = -0.5f * L2E;
    float lb[8];
#pragma unroll
    for (int k = 0; k < 8; k++) lb[k] = (acc[k] + c) * sc;

    __syncthreads();                      // xs conv reads done; reuse as logB buffer
#pragma unroll
    for (int k = 0; k < 8; k++) xs[(rg * 8 + k) * 64 + s] = lb[k];
    __syncthreads();

    // per-row max + z write: warp w handles rows 4w..4w+3
    int w = tid >> 5, lane = tid & 31;
#pragma unroll
    for (int j = 0; j < 4; j++) {
        int r = 4 * w + j;
        float v0 = xs[r * 64 + lane];
        float v1 = xs[r * 64 + 32 + lane];
        float m = fmaxf(v0, v1);
#pragma unroll
        for (int o = 16; o; o >>= 1) m = fmaxf(m, __shfl_xor_sync(0xffffffffu, m, o));
        size_t base = (bt0 + r) * NS;
        g_z[base + lane]      = ex2f(v0 - m);
        g_z[base + lane + 32] = ex2f(v1 - m);
        if (lane == 0) g_c[bt0 + r] = m;
    }
}

// ---------------- per-batch sum of c (double) ----------------
__global__ void csum_kernel()
{
    int b = (int)(threadIdx.x >> 5);
    int lane = threadIdx.x & 31;
    double s = 0.0;
    for (int t = lane; t < NT; t += 32) s += (double)g_c[b * NT + t];
#pragma unroll
    for (int o = 16; o; o >>= 1) s += __shfl_xor_sync(0xffffffffu, s, o);
    if (lane == 0) g_csum[b] = s;
}

// ---------------- linear-domain HSMM scan: one CTA (64 thr) per batch ----------------
// thread = state s. Ring of 32 linear "trans mass" values per state in registers
// (36-reg sliding window, t unrolled x4). Per step:
//   ring *= z[s]*rho ; acc = sum_d Dur[d]*ring[d] ; q = A^T acc (smem broadcast) ; insert q.
// DAMPED normalization controller (eta = 1/2): rho = 2^(16 - lg2(qmax)/2), from a
// lagged qmax reduction running in the shadow of the main path. Lagged feedback
// L_{t+1}=L_t-eta*L_{t-1}+c has |roots|=sqrt(eta)<1 -> no resonance.
// Exact ledger: acc_meas = acc_true * 2^{-csum} * PROD(rho); pend = -lg2(rho);
// true log = lg2(acc_meas) + csum + rr  (rr = sum of pend).  [sign fixed in R5]
__global__ void __launch_bounds__(64, 1) scan_kernel(float* __restrict__ out)
{
    __shared__ float sm_acc[2][NS];
    __shared__ float sm_wmax[2][2];     // [warp][parity]
    __shared__ float sm_part[2];

    int b = blockIdx.x;
    int s = threadIdx.x;
    int wid = s >> 5, lane = s & 31;

    // per-thread constants
    float Acol[64];
    const float4* at4 = (const float4*)(g_AT + (size_t)s * NS);
#pragma unroll
    for (int j = 0; j < 16; j++) {
        float4 v = at4[j];
        Acol[4 * j] = v.x; Acol[4 * j + 1] = v.y; Acol[4 * j + 2] = v.z; Acol[4 * j + 3] = v.w;
    }
    float durk[32];                       // durk[k] pairs ring slot: d = 32-k (row d-1 = 31-k)
#pragma unroll
    for (int k = 0; k < 32; k++) durk[k] = g_DurT[(31 - k) * NS + s];

    float W[36];
#pragma unroll
    for (int j = 0; j < 36; j++) W[j] = 0.f;
    W[31] = 0.015625f;                    // logpi seed: becomes the d=t+1 slot at every t

    const float* zp = g_z + (size_t)b * NT * NS + s;
    float zq[4];
#pragma unroll
    for (int i = 0; i < 4; i++) zq[i] = zp[(size_t)i * NS];

    if (s < 2) { sm_wmax[s][0] = 4294967296.0f; sm_wmax[s][1] = 4294967296.0f; }
    float qprev = 4294967296.0f;          // first measured qmax -> rho == 1, pend == 0
    float rho = 1.0f;
    float pend = 0.0f;
    double rr = 0.0;
    float lastacc = 0.f;
    __syncthreads();

    for (int t4 = 0; t4 < NT; t4 += 4) {
#pragma unroll
        for (int i = 0; i < 4; i++) {
            const int par = i & 1;        // == t & 1
            float mlt = zq[i] * rho;
            zq[i] = zp[(size_t)(t4 + i + 4) * NS];   // prefetch (array padded)
            rr += (double)pend;

            // conv over durations + persistent ring rescale (all registers)
            float a0 = 0.f, a1 = 0.f, a2 = 0.f, a3 = 0.f;
#pragma unroll
            for (int k = 0; k < 32; k += 4) {
                W[k + i]     *= mlt; a0 = fmaf(durk[k],     W[k + i],     a0);
                W[k + 1 + i] *= mlt; a1 = fmaf(durk[k + 1], W[k + 1 + i], a1);
                W[k + 2 + i] *= mlt; a2 = fmaf(durk[k + 2], W[k + 2 + i], a2);
                W[k + 3 + i] *= mlt; a3 = fmaf(durk[k + 3], W[k + 3 + i], a3);
            }
            float acc = (a0 + a1) + (a2 + a3);
            lastacc = acc;

            // shadow reduction of previous q (off critical path)
            float wm = qprev;
            wm = fmaxf(wm, __shfl_xor_sync(0xffffffffu, wm, 16));
            wm = fmaxf(wm, __shfl_xor_sync(0xffffffffu, wm, 8));
            wm = fmaxf(wm, __shfl_xor_sync(0xffffffffu, wm, 4));
            wm = fmaxf(wm, __shfl_xor_sync(0xffffffffu, wm, 2));
            wm = fmaxf(wm, __shfl_xor_sync(0xffffffffu, wm, 1));
            if (lane == 0) sm_wmax[wid][par] = wm;

            sm_acc[par][s] = acc;
            __syncthreads();

            // damped controller: rho = 2^(16 - lg2(qmax)/2)
            float qmax = fmaxf(sm_wmax[0][par], sm_wmax[1][par]);
            qmax = fminf(fmaxf(qmax, 1e-30f), 1e30f);
            float hl = 0.5f * lg2f(qmax);
            rho  = ex2f(16.0f - hl);
            pend = hl - 16.0f;

            // matvec: q[s] = sum_{s'} A[s'][s] * acc[s']   (smem broadcast reads)
            float q0 = 0.f, q1 = 0.f, q2 = 0.f, q3 = 0.f;
            const float4* ap = (const float4*)sm_acc[par];
#pragma unroll
            for (int j = 0; j < 16; j++) {
                float4 v = ap[j];
                q0 = fmaf(Acol[4 * j],     v.x, q0);
                q1 = fmaf(Acol[4 * j + 1], v.y, q1);
                q2 = fmaf(Acol[4 * j + 2], v.z, q2);
                q3 = fmaf(Acol[4 * j + 3], v.w, q3);
            }
            float q = (q0 + q1) + (q2 + q3);
            W[32 + i] = q;                // becomes d=1 next step
            qprev = q;
        }
        // slide the window by 4
#pragma unroll
        for (int j = 0; j < 32; j++) W[j] = W[j + 4];
    }

    // final: out[b] = ln2 * ( lg2(sum_s acc) + csum + rr )
    float v = lastacc;
#pragma unroll
    for (int o = 16; o; o >>= 1) v += __shfl_xor_sync(0xffffffffu, v, o);
    if (lane == 0) sm_part[wid] = v;
    __syncthreads();
    if (s == 0) {
        float tot = sm_part[0] + sm_part[1];
        double res = (double)lg2f(tot) + g_csum[b] + rr;
        out[b] = (float)(res * LN2D);
    }
}

// ---------------- host launcher (exactly 6 launches; scan is #6 for ncu -s 5 -c 1) -------------
extern "C" void kernel_launch(void* const* d_in, const int* in_sizes, int n_in,
                              void* d_out, int out_size)
{
    const float* x        = (const float*)d_in[0];
    const float* context  = (const float*)d_in[1];
    const float* A_logits = (const float*)d_in[2];
    const float* D_logits = (const float*)d_in[3];
    const float* mu       = (const float*)d_in[4];
    const float* log_var  = (const float*)d_in[5];
    const float* tA_w1 = (const float*)d_in[6],  *tA_b1 = (const float*)d_in[7];
    const float* tA_w2 = (const float*)d_in[8],  *tA_b2 = (const float*)d_in[9];
    const float* tD_w1 = (const float*)d_in[10], *tD_b1 = (const float*)d_in[11];
    const float* tD_w2 = (const float*)d_in[12], *tD_b2 = (const float*)d_in[13];
    const float* tE_w1 = (const float*)d_in[14], *tE_b1 = (const float*)d_in[15];
    const float* tE_w2 = (const float*)d_in[16], *tE_b2 = (const float*)d_in[17];

    lin1_kernel<<<1280, 256>>>(context, tA_w1, tA_b1, tD_w1, tD_b1, tE_w1, tE_b1);
    lin2_kernel<<<1280, 256>>>(tA_w2, tA_b2, tD_w2, tD_b2, tE_w2, tE_b2);
    post_kernel<<<NS, 32>>>(A_logits, D_logits, mu, log_var);
    logbz_kernel<<<(NB * NT) / 32, 256>>>(x);
    csum_kernel<<<1, 1024>>>();
    scan_kernel<<<NB, 64>>>((float*)d_out);
}